// round 15
// baseline (speedup 1.0000x reference)
#include <cuda_runtime.h>

typedef unsigned long long ull;

// Problem constants
#define BB   64
#define SD   14
#define NS   196          // S*S
#define CC   32
#define OO   10
#define OPAD 16           // o padded to 16 lanes for warp-local softmax
#define HH   16
#define EPSV 1e-9f
#define LOG2E 1.4426950408889634f
#define LN2PI 1.8378770664093453f
#define SCHUNK 28         // spatial positions per block (= 2 rows of 14)
#define NBLK_S 7          // 196 / 28
#define CPB  16           // channels per block

#define BO (BB*OO)        // 640
#define ACC_STRIDE 33     // s0, s1[16], s2[16]
#define MOM_STRIDE 72     // per-(b,c) moment record (69 used)
#define NBC (BB*CC)       // 2048

// ---- packed f32x2 helpers (FFMA2 path; sm_100+) ----
__device__ __forceinline__ ull pk(float lo, float hi) {
    ull r; asm("mov.b64 %0, {%1, %2};" : "=l"(r) : "f"(lo), "f"(hi)); return r;
}
__device__ __forceinline__ void upk(float& lo, float& hi, ull p) {
    asm("mov.b64 {%0, %1}, %2;" : "=f"(lo), "=f"(hi) : "l"(p));
}
__device__ __forceinline__ ull fma2(ull a, ull b, ull c) {
    ull d; asm("fma.rn.f32x2 %0, %1, %2, %3;" : "=l"(d) : "l"(a), "l"(b), "l"(c)); return d;
}
__device__ __forceinline__ ull mul2(ull a, ull b) {
    ull d; asm("mul.rn.f32x2 %0, %1, %2;" : "=l"(d) : "l"(a), "l"(b)); return d;
}
__device__ __forceinline__ ull add2(ull a, ull b) {
    ull d; asm("add.rn.f32x2 %0, %1, %2;" : "=l"(d) : "l"(a), "l"(b)); return d;
}

// Scratch
__device__ float g_acc[3][BO*ACC_STRIDE];
__device__ float g_par[2][BO*ACC_STRIDE];
__device__ float g_mom[NBC*MOM_STRIDE];

#define NZERO (3*BO*ACC_STRIDE + NBC*MOM_STRIDE)

__global__ void zero_kernel() {
    int i = blockIdx.x * blockDim.x + threadIdx.x;
    if (i < 3 * BO * ACC_STRIDE) ((float*)g_acc)[i] = 0.0f;
    int j = i - 3 * BO * ACC_STRIDE;
    if (j >= 0 && j < NBC * MOM_STRIDE) g_mom[j] = 0.0f;
}

// ---------------------------------------------------------------------------
// Iteration-0 stats via per-(b,c) pose moments (rr = 1/O is uniform).
// ---------------------------------------------------------------------------
__global__ __launch_bounds__(256)
void moment_kernel(const float* __restrict__ pose,
                   const float* __restrict__ act)
{
    const int c = threadIdx.x;
    const int q = blockIdx.y * 8 + threadIdx.y;   // 0..15
    const int b = blockIdx.x;

    float A0 = 0.0f, Ar = 0.0f, Ac = 0.0f, SR2 = 0.0f, SC2 = 0.0f;
    float P[16], M[40], PR[4], PC[4];
    #pragma unroll
    for (int j = 0; j < 16; j++) P[j] = 0.0f;
    #pragma unroll
    for (int j = 0; j < 40; j++) M[j] = 0.0f;
    #pragma unroll
    for (int j = 0; j < 4; j++) { PR[j] = 0.0f; PC[j] = 0.0f; }

    for (int s = q; s < NS; s += 16) {
        const float4* p4 = reinterpret_cast<const float4*>(pose)
                           + ((size_t)(b * NS + s) * CC + c) * 4;
        float p[16];
        #pragma unroll
        for (int i = 0; i < 4; i++) {
            float4 r = p4[i];
            p[i*4+0] = r.x; p[i*4+1] = r.y; p[i*4+2] = r.z; p[i*4+3] = r.w;
        }
        const float a = act[(size_t)(b * NS + s) * CC + c];

        A0 += a;
        int idx = 0;
        #pragma unroll
        for (int i = 0; i < 4; i++) {
            #pragma unroll
            for (int j = 0; j < 4; j++) {
                float tt = a * p[i*4+j];
                P[i*4+j] += tt;
                #pragma unroll
                for (int j2 = j; j2 < 4; j2++)
                    M[idx++] += tt * p[i*4+j2];
            }
        }
        const int sr = s / SD, sc = s - sr * SD;
        const float cr = (sr + 0.5f) * (1.0f / SD);
        const float cc = (sc + 0.5f) * (1.0f / SD);
        const float acr = a * cr, acc = a * cc;
        Ar += acr; Ac += acc;
        SR2 += acr * cr; SC2 += acc * cc;
        #pragma unroll
        for (int j = 0; j < 4; j++) { PR[j] += acr * p[j]; PC[j] += acc * p[j]; }
    }

    float* dst = &g_mom[(b * CC + c) * MOM_STRIDE];
    atomicAdd(dst + 0, A0);
    #pragma unroll
    for (int j = 0; j < 16; j++) atomicAdd(dst + 1 + j, P[j]);
    #pragma unroll
    for (int j = 0; j < 40; j++) atomicAdd(dst + 17 + j, M[j]);
    atomicAdd(dst + 57, Ar); atomicAdd(dst + 58, Ac);
    #pragma unroll
    for (int j = 0; j < 4; j++) { atomicAdd(dst + 59 + j, PR[j]); atomicAdd(dst + 63 + j, PC[j]); }
    atomicAdd(dst + 67, SR2); atomicAdd(dst + 68, SC2);
}

// Contract moments against w -> g_acc[0] (iteration-0 S0/S1/S2).
__global__ void init_stats_kernel(const float* __restrict__ w)
{
    const int tid = blockIdx.x * blockDim.x + threadIdx.x;
    if (tid >= BB * OO * 4) return;
    const int i = tid & 3;
    const int o = (tid >> 2) % OO;
    const int b = tid / (OO * 4);

    float S1[4] = {0, 0, 0, 0}, S2[4] = {0, 0, 0, 0};
    float A0t = 0.0f;

    for (int c = 0; c < CC; c++) {
        const float* mm = &g_mom[(b * CC + c) * MOM_STRIDE];
        const float* wc = &w[(c * OO + o) * 16];
        float P[4], Ms[10];
        #pragma unroll
        for (int j = 0; j < 4; j++) P[j] = mm[1 + i * 4 + j];
        #pragma unroll
        for (int tt = 0; tt < 10; tt++) Ms[tt] = mm[17 + i * 10 + tt];

        #pragma unroll
        for (int k = 0; k < 4; k++) {
            float wk[4];
            #pragma unroll
            for (int j = 0; j < 4; j++) wk[j] = wc[j * 4 + k];
            S1[k] += P[0]*wk[0] + P[1]*wk[1] + P[2]*wk[2] + P[3]*wk[3];
            float s2 = 0.0f; int idx = 0;
            #pragma unroll
            for (int j = 0; j < 4; j++) {
                s2 += Ms[idx++] * wk[j] * wk[j];
                #pragma unroll
                for (int j2 = j + 1; j2 < 4; j2++)
                    s2 += 2.0f * Ms[idx++] * wk[j] * wk[j2];
            }
            S2[k] += s2;
        }
        if (i == 0) {
            A0t += mm[0];
            float pr = 0.0f, pc = 0.0f;
            #pragma unroll
            for (int j = 0; j < 4; j++) {
                pr += mm[59 + j] * wc[j * 4 + 0];
                pc += mm[63 + j] * wc[j * 4 + 1];
            }
            S1[0] += mm[57];  S1[1] += mm[58];
            S2[0] += 2.0f * pr + mm[67];
            S2[1] += 2.0f * pc + mm[68];
        }
    }

    float* dst = &g_acc[0][(b * OO + o) * ACC_STRIDE];
    #pragma unroll
    for (int k = 0; k < 4; k++) {
        dst[1 + i * 4 + k]  = S1[k] * 0.1f;
        dst[17 + i * 4 + k] = S2[k] * 0.1f;
    }
    if (i == 0) dst[0] = A0t * 0.1f;
}

// ---------------------------------------------------------------------------
// Fused sweep (iterations 1,2): rr-update softmax + stats.
// SOFTWARE-PIPELINED: position si+1's votes/lap (independent smem loads +
// packed FMA) are computed BEFORE position si's shuffle/exp/div/accumulate,
// so the butterfly+MUFU chain is hidden behind the next stage's work.
// ---------------------------------------------------------------------------
__device__ __forceinline__ void vote_lap_stage(
    int si, int c_local, int o, int base_row, float c1r,
    const float4* sm_pose4, const float* sm_act,
    const ull (*sm_Sh2)[9], const ull (*sm_nMSh2)[9],
    const ull wp[4][2],
    ull v2[8], float& lap, float& a)
{
    const float4* p4 = &sm_pose4[(si * CPB + c_local) * 4];
    #pragma unroll
    for (int i = 0; i < 4; i++) {
        float4 p = p4[i];
        ull px = pk(p.x, p.x), py = pk(p.y, p.y);
        ull pz = pk(p.z, p.z), pw = pk(p.w, p.w);
        #pragma unroll
        for (int kp = 0; kp < 2; kp++) {
            ull tv = mul2(px, wp[0][kp]);
            tv = fma2(py, wp[1][kp], tv);
            tv = fma2(pz, wp[2][kp], tv);
            tv = fma2(pw, wp[3][kp], tv);
            v2[i * 2 + kp] = tv;
        }
    }
    const int row1 = (si >= SD) ? 1 : 0;
    v2[0] = add2(v2[0], pk((base_row + row1 + 0.5f) * (1.0f / SD),
                           (si - row1 * SD + 0.5f) * (1.0f / SD)));
    a = sm_act[si * CPB + c_local];

    ull sqa = 0ULL, sqb = 0ULL;
    #pragma unroll
    for (int hp = 0; hp < 8; hp += 2) {
        ull dA = fma2(v2[hp],     sm_Sh2[o][hp],     sm_nMSh2[o][hp]);
        ull dB = fma2(v2[hp + 1], sm_Sh2[o][hp + 1], sm_nMSh2[o][hp + 1]);
        sqa = fma2(dA, dA, sqa);
        sqb = fma2(dB, dB, sqb);
    }
    float qa0, qa1, qb0, qb1;
    upk(qa0, qa1, sqa); upk(qb0, qb1, sqb);
    lap = c1r - ((qa0 + qa1) + (qb0 + qb1));
}

__global__ __launch_bounds__(256, 2)
void pass_kernel(const float* __restrict__ pose,
                 const float* __restrict__ act,
                 const float* __restrict__ w,
                 int par_idx, int acc_idx)
{
    const int t = threadIdx.x;
    const int o = t & (OPAD - 1);
    const int c_local = t >> 4;
    const int cbase = blockIdx.y * CPB;
    const int c = cbase + c_local;
    const int b = blockIdx.z;
    const int sbase = blockIdx.x * SCHUNK;
    const bool live = (o < OO);

    __shared__ float4 sm_pose4[SCHUNK * CPB * 4];
    __shared__ float  sm_act[SCHUNK * CPB];
    __shared__ ull    sm_Sh2[OPAD][9];
    __shared__ ull    sm_nMSh2[OPAD][9];
    __shared__ float  sm_c1[OPAD];

    ull wp[4][2];
    {
        float wr[16];
        #pragma unroll
        for (int j = 0; j < 16; j++)
            wr[j] = live ? w[(c * OO + o) * 16 + j] : 0.0f;
        #pragma unroll
        for (int j = 0; j < 4; j++)
            #pragma unroll
            for (int kp = 0; kp < 2; kp++)
                wp[j][kp] = pk(wr[j * 4 + 2 * kp], wr[j * 4 + 2 * kp + 1]);
    }

    if (t < OPAD) sm_c1[t] = -1e30f;
    if (t < OPAD * 9) { sm_Sh2[t / 9][t % 9] = 0ULL; sm_nMSh2[t / 9][t % 9] = 0ULL; }
    __syncthreads();

    {
        const float4* gpose4 = reinterpret_cast<const float4*>(pose);
        #pragma unroll
        for (int k = 0; k < 7; k++) {
            int i = t + k * 256;
            int row = i >> 6;
            int col = i & 63;
            sm_pose4[row * 64 + col] =
                gpose4[((size_t)(b * NS + sbase + row) * CC + cbase) * 4 + col];
        }
        for (int i = t; i < SCHUNK * CPB; i += 256) {
            int row = i >> 4, cc = i & 15;
            sm_act[i] = act[(size_t)(b * NS + sbase + row) * CC + cbase + cc];
        }
    }
    if (t < 80) {
        int oo = t >> 3, hp = t & 7;
        const float* pp = &g_par[par_idx][(b * OO + oo) * ACC_STRIDE];
        sm_Sh2[oo][hp]   = pk(pp[1 + 2 * hp], pp[2 + 2 * hp]);
        sm_nMSh2[oo][hp] = pk(-pp[17 + 2 * hp], -pp[18 + 2 * hp]);
    } else if (t < 90) {
        int oo = t - 80;
        sm_c1[oo] = g_par[par_idx][(b * OO + oo) * ACC_STRIDE];
    }
    __syncthreads();
    const float c1r = sm_c1[o];

    float a0 = 0.0f;
    ull a1p[8], a2p[8];
    #pragma unroll
    for (int hp = 0; hp < 8; hp++) { a1p[hp] = 0ULL; a2p[hp] = 0ULL; }

    const int base_row = sbase / SD;

    // prologue: stage position 0
    ull v2c[8]; float lapc, ac;
    vote_lap_stage(0, c_local, o, base_row, c1r,
                   sm_pose4, sm_act, sm_Sh2, sm_nMSh2, wp, v2c, lapc, ac);

    #pragma unroll 2
    for (int si = 0; si < SCHUNK; si++) {
        // stage si+1 (independent work, hides the butterfly/MUFU chain below)
        ull v2n[8]; float lapn, an;
        const int sj = (si + 1 < SCHUNK) ? (si + 1) : (SCHUNK - 1);
        vote_lap_stage(sj, c_local, o, base_row, c1r,
                       sm_pose4, sm_act, sm_Sh2, sm_nMSh2, wp, v2n, lapn, an);

        // finish position si: softmax + accumulate
        float e = exp2f(lapc);
        float sum = e;
        #pragma unroll
        for (int m = 8; m >= 1; m >>= 1)
            sum += __shfl_xor_sync(0xFFFFFFFFu, sum, m);
        if (__any_sync(0xFFFFFFFFu, sum < 1e-30f)) {
            float mx = lapc;
            #pragma unroll
            for (int m = 8; m >= 1; m >>= 1)
                mx = fmaxf(mx, __shfl_xor_sync(0xFFFFFFFFu, mx, m));
            e = exp2f(lapc - mx);
            sum = e;
            #pragma unroll
            for (int m = 8; m >= 1; m >>= 1)
                sum += __shfl_xor_sync(0xFFFFFFFFu, sum, m);
        }
        float r = e * __fdividef(ac, sum);

        a0 += r;
        ull r2 = pk(r, r);
        #pragma unroll
        for (int hp = 0; hp < 8; hp++) {
            ull rv = mul2(r2, v2c[hp]);
            a1p[hp] = add2(a1p[hp], rv);
            a2p[hp] = fma2(rv, v2c[hp], a2p[hp]);
        }

        // rotate stage (register rename under unroll 2)
        #pragma unroll
        for (int hp = 0; hp < 8; hp++) v2c[hp] = v2n[hp];
        lapc = lapn; ac = an;
    }

    float a1[16], a2[16];
    #pragma unroll
    for (int hp = 0; hp < 8; hp++) {
        upk(a1[2 * hp], a1[2 * hp + 1], a1p[hp]);
        upk(a2[2 * hp], a2[2 * hp + 1], a2p[hp]);
    }

    a0 += __shfl_down_sync(0xFFFFFFFFu, a0, 16);
    #pragma unroll
    for (int h = 0; h < 16; h++) {
        a1[h] += __shfl_down_sync(0xFFFFFFFFu, a1[h], 16);
        a2[h] += __shfl_down_sync(0xFFFFFFFFu, a2[h], 16);
    }

    if ((t & 31) < OO) {
        float* dst = &g_acc[acc_idx][(b * OO + o) * ACC_STRIDE];
        atomicAdd(dst, a0);
        #pragma unroll
        for (int h = 0; h < 16; h++) {
            atomicAdd(dst + 1 + h, a1[h]);
            atomicAdd(dst + 17 + h, a2[h]);
        }
    }
}

// ---------------------------------------------------------------------------
// M-step, parallelized over (b,o,h): 16 blocks x 640 thr (4 batches/block).
// ---------------------------------------------------------------------------
__global__ __launch_bounds__(640)
void m_kernel(const float* __restrict__ beta_a,
              const float* __restrict__ beta_v,
              float* __restrict__ out,
              int acc_idx, int par_idx,
              float inv_temp, int is_final)
{
    __shared__ float sc1[4][OO];
    const int t = threadIdx.x;
    const int h = t & 15;
    const int o = (t >> 4) % OO;
    const int bl = t / (OO * 16);          // 0..3
    const int b = blockIdx.x * 4 + bl;
    const int idx = b * OO + o;

    const float* sacc = &g_acc[acc_idx][idx * ACC_STRIDE];
    const float s0 = sacc[0];
    const float denom = __fdividef(1.0f, s0 + EPSV);

    const float s1 = sacc[1 + h];
    const float s2 = sacc[17 + h];
    const float mh = s1 * denom;
    const float num = s2 - 2.0f * mh * s1 + mh * mh * s0;
    const float vh = num * denom + EPSV;

    float sumlog = __logf(vh);
    #pragma unroll
    for (int m = 8; m >= 1; m >>= 1)
        sumlog += __shfl_xor_sync(0xFFFFFFFFu, sumlog, m);

    const float cost = (16.0f * beta_v[o] + 0.5f * sumlog) * s0;
    const float aj = __fdividef(1.0f, 1.0f + __expf(-inv_temp * (beta_a[o] - cost)));

    if (is_final) {
        out[idx * 16 + h] = mh;
        if (h == 0) out[BO * 16 + idx] = aj;
    } else {
        float* pp = &g_par[par_idx][idx * ACC_STRIDE];
        const float S = 0.84932180028801904f * rsqrtf(vh);  // sqrt(log2e/2)/sqrt(var)
        pp[1 + h] = S;
        pp[17 + h] = mh * S;
        const float c1l2 = (__logf(aj + EPSV)
                            - 0.5f * (16.0f * LN2PI + sumlog)) * LOG2E;
        if (h == 0) sc1[bl][o] = c1l2;
        __syncthreads();
        if (h == 0) {
            float mx = sc1[bl][0];
            #pragma unroll
            for (int oo = 1; oo < OO; oo++) mx = fmaxf(mx, sc1[bl][oo]);
            pp[0] = c1l2 - mx;
        }
    }
}

extern "C" void kernel_launch(void* const* d_in, const int* in_sizes, int n_in,
                              void* d_out, int out_size)
{
    const float* pose = (const float*)d_in[0];
    const float* act  = (const float*)d_in[1];
    const float* w    = (const float*)d_in[2];
    const float* ba   = (const float*)d_in[3];
    const float* bv   = (const float*)d_in[4];
    float* out = (float*)d_out;

    zero_kernel<<<(NZERO + 255) / 256, 256>>>();

    const float it0 = 0.01f * (1.0f - 0.95f);
    const float it1 = 0.01f * (1.0f - 0.95f * 0.95f);
    const float it2 = 0.01f * (1.0f - 0.95f * 0.95f * 0.95f);

    // iteration 0 via pose moments (no vote sweep)
    moment_kernel<<<dim3(BB, 2), dim3(32, 8)>>>(pose, act);
    init_stats_kernel<<<10, 256>>>(w);
    m_kernel<<<16, 640>>>(ba, bv, out, 0, 0, it0, 0);

    // iterations 1-2: fused rr-update + stats sweeps
    dim3 grid(NBLK_S, 2, BB);
    pass_kernel<<<grid, 256>>>(pose, act, w, 0, 1);
    m_kernel<<<16, 640>>>(ba, bv, out, 1, 1, it1, 0);
    pass_kernel<<<grid, 256>>>(pose, act, w, 1, 2);
    m_kernel<<<16, 640>>>(ba, bv, out, 2, 0, it2, 1);
}

// round 16
// speedup vs baseline: 1.0968x; 1.0968x over previous
#include <cuda_runtime.h>

typedef unsigned long long ull;

// Problem constants
#define BB   64
#define SD   14
#define NS   196          // S*S
#define CC   32
#define OO   10
#define OPAD 16           // o padded to 16 lanes for warp-local softmax
#define HH   16
#define EPSV 1e-9f
#define LOG2E 1.4426950408889634f
#define LN2PI 1.8378770664093453f
#define SCHUNK 28         // spatial positions per block (= 2 rows of 14)
#define NBLK_S 7          // 196 / 28
#define CPB  16           // channels per block

#define BO (BB*OO)        // 640
#define ACC_STRIDE 33     // s0, s1[16], s2[16]
#define MOM_STRIDE 72     // per-(b,c) moment record (69 used)
#define NBC (BB*CC)       // 2048

// ---- packed f32x2 helpers (FFMA2 path; sm_100+) ----
__device__ __forceinline__ ull pk(float lo, float hi) {
    ull r; asm("mov.b64 %0, {%1, %2};" : "=l"(r) : "f"(lo), "f"(hi)); return r;
}
__device__ __forceinline__ void upk(float& lo, float& hi, ull p) {
    asm("mov.b64 {%0, %1}, %2;" : "=f"(lo), "=f"(hi) : "l"(p));
}
__device__ __forceinline__ ull fma2(ull a, ull b, ull c) {
    ull d; asm("fma.rn.f32x2 %0, %1, %2, %3;" : "=l"(d) : "l"(a), "l"(b), "l"(c)); return d;
}
__device__ __forceinline__ ull mul2(ull a, ull b) {
    ull d; asm("mul.rn.f32x2 %0, %1, %2;" : "=l"(d) : "l"(a), "l"(b)); return d;
}
__device__ __forceinline__ ull add2(ull a, ull b) {
    ull d; asm("add.rn.f32x2 %0, %1, %2;" : "=l"(d) : "l"(a), "l"(b)); return d;
}

// Scratch
__device__ float g_acc[3][BO*ACC_STRIDE];
__device__ float g_par[2][BO*ACC_STRIDE];
__device__ float g_mom[NBC*MOM_STRIDE];

#define NZERO (3*BO*ACC_STRIDE + NBC*MOM_STRIDE)

__global__ void zero_kernel() {
    int i = blockIdx.x * blockDim.x + threadIdx.x;
    if (i < 3 * BO * ACC_STRIDE) ((float*)g_acc)[i] = 0.0f;
    int j = i - 3 * BO * ACC_STRIDE;
    if (j >= 0 && j < NBC * MOM_STRIDE) g_mom[j] = 0.0f;
}

// ---------------------------------------------------------------------------
// Iteration-0 stats via per-(b,c) pose moments (rr = 1/O is uniform).
// ---------------------------------------------------------------------------
__global__ __launch_bounds__(256)
void moment_kernel(const float* __restrict__ pose,
                   const float* __restrict__ act)
{
    const int c = threadIdx.x;
    const int q = blockIdx.y * 8 + threadIdx.y;   // 0..15
    const int b = blockIdx.x;

    float A0 = 0.0f, Ar = 0.0f, Ac = 0.0f, SR2 = 0.0f, SC2 = 0.0f;
    float P[16], M[40], PR[4], PC[4];
    #pragma unroll
    for (int j = 0; j < 16; j++) P[j] = 0.0f;
    #pragma unroll
    for (int j = 0; j < 40; j++) M[j] = 0.0f;
    #pragma unroll
    for (int j = 0; j < 4; j++) { PR[j] = 0.0f; PC[j] = 0.0f; }

    for (int s = q; s < NS; s += 16) {
        const float4* p4 = reinterpret_cast<const float4*>(pose)
                           + ((size_t)(b * NS + s) * CC + c) * 4;
        float p[16];
        #pragma unroll
        for (int i = 0; i < 4; i++) {
            float4 r = p4[i];
            p[i*4+0] = r.x; p[i*4+1] = r.y; p[i*4+2] = r.z; p[i*4+3] = r.w;
        }
        const float a = act[(size_t)(b * NS + s) * CC + c];

        A0 += a;
        int idx = 0;
        #pragma unroll
        for (int i = 0; i < 4; i++) {
            #pragma unroll
            for (int j = 0; j < 4; j++) {
                float tt = a * p[i*4+j];
                P[i*4+j] += tt;
                #pragma unroll
                for (int j2 = j; j2 < 4; j2++)
                    M[idx++] += tt * p[i*4+j2];
            }
        }
        const int sr = s / SD, sc = s - sr * SD;
        const float cr = (sr + 0.5f) * (1.0f / SD);
        const float cc = (sc + 0.5f) * (1.0f / SD);
        const float acr = a * cr, acc = a * cc;
        Ar += acr; Ac += acc;
        SR2 += acr * cr; SC2 += acc * cc;
        #pragma unroll
        for (int j = 0; j < 4; j++) { PR[j] += acr * p[j]; PC[j] += acc * p[j]; }
    }

    float* dst = &g_mom[(b * CC + c) * MOM_STRIDE];
    atomicAdd(dst + 0, A0);
    #pragma unroll
    for (int j = 0; j < 16; j++) atomicAdd(dst + 1 + j, P[j]);
    #pragma unroll
    for (int j = 0; j < 40; j++) atomicAdd(dst + 17 + j, M[j]);
    atomicAdd(dst + 57, Ar); atomicAdd(dst + 58, Ac);
    #pragma unroll
    for (int j = 0; j < 4; j++) { atomicAdd(dst + 59 + j, PR[j]); atomicAdd(dst + 63 + j, PC[j]); }
    atomicAdd(dst + 67, SR2); atomicAdd(dst + 68, SC2);
}

// Contract moments against w -> g_acc[0] (iteration-0 S0/S1/S2).
__global__ void init_stats_kernel(const float* __restrict__ w)
{
    const int tid = blockIdx.x * blockDim.x + threadIdx.x;
    if (tid >= BB * OO * 4) return;
    const int i = tid & 3;
    const int o = (tid >> 2) % OO;
    const int b = tid / (OO * 4);

    float S1[4] = {0, 0, 0, 0}, S2[4] = {0, 0, 0, 0};
    float A0t = 0.0f;

    for (int c = 0; c < CC; c++) {
        const float* mm = &g_mom[(b * CC + c) * MOM_STRIDE];
        const float* wc = &w[(c * OO + o) * 16];
        float P[4], Ms[10];
        #pragma unroll
        for (int j = 0; j < 4; j++) P[j] = mm[1 + i * 4 + j];
        #pragma unroll
        for (int tt = 0; tt < 10; tt++) Ms[tt] = mm[17 + i * 10 + tt];

        #pragma unroll
        for (int k = 0; k < 4; k++) {
            float wk[4];
            #pragma unroll
            for (int j = 0; j < 4; j++) wk[j] = wc[j * 4 + k];
            S1[k] += P[0]*wk[0] + P[1]*wk[1] + P[2]*wk[2] + P[3]*wk[3];
            float s2 = 0.0f; int idx = 0;
            #pragma unroll
            for (int j = 0; j < 4; j++) {
                s2 += Ms[idx++] * wk[j] * wk[j];
                #pragma unroll
                for (int j2 = j + 1; j2 < 4; j2++)
                    s2 += 2.0f * Ms[idx++] * wk[j] * wk[j2];
            }
            S2[k] += s2;
        }
        if (i == 0) {
            A0t += mm[0];
            float pr = 0.0f, pc = 0.0f;
            #pragma unroll
            for (int j = 0; j < 4; j++) {
                pr += mm[59 + j] * wc[j * 4 + 0];
                pc += mm[63 + j] * wc[j * 4 + 1];
            }
            S1[0] += mm[57];  S1[1] += mm[58];
            S2[0] += 2.0f * pr + mm[67];
            S2[1] += 2.0f * pc + mm[68];
        }
    }

    float* dst = &g_acc[0][(b * OO + o) * ACC_STRIDE];
    #pragma unroll
    for (int k = 0; k < 4; k++) {
        dst[1 + i * 4 + k]  = S1[k] * 0.1f;
        dst[17 + i * 4 + k] = S2[k] * 0.1f;
    }
    if (i == 0) dst[0] = A0t * 0.1f;
}

// ---------------------------------------------------------------------------
// Fused sweep (iterations 1,2): rr-update softmax + stats.  R14 structure,
// but w lives in PADDED SHARED MEMORY instead of 16 registers -> relieves
// the 128-reg ceiling (spill/remat pressure).  Per-(c,o) stride 9 ull keeps
// the per-iteration weight reads >=8-distinct-bank (worst 2-way conflict).
// ---------------------------------------------------------------------------
__global__ __launch_bounds__(256, 2)
void pass_kernel(const float* __restrict__ pose,
                 const float* __restrict__ act,
                 const float* __restrict__ w,
                 int par_idx, int acc_idx)
{
    const int t = threadIdx.x;
    const int o = t & (OPAD - 1);
    const int c_local = t >> 4;
    const int cbase = blockIdx.y * CPB;
    const int b = blockIdx.z;
    const int sbase = blockIdx.x * SCHUNK;
    const bool live = (o < OO);
    const int o_ld = live ? o : (OO - 1);   // dummy lanes read o=9's w (r=0 anyway)

    __shared__ float4 sm_pose4[SCHUNK * CPB * 4];        // 28 KB
    __shared__ float  sm_act[SCHUNK * CPB];              // 1.75 KB
    __shared__ ull    sm_w2[CPB * OO * 9];               // 11.25 KB, stride-9 pad
    __shared__ ull    sm_Sh2[OPAD][9];
    __shared__ ull    sm_nMSh2[OPAD][9];
    __shared__ float  sm_c1[OPAD];

    if (t < OPAD) sm_c1[t] = -1e30f;
    if (t < OPAD * 9) { sm_Sh2[t / 9][t % 9] = 0ULL; sm_nMSh2[t / 9][t % 9] = 0ULL; }
    __syncthreads();

    {
        const float4* gpose4 = reinterpret_cast<const float4*>(pose);
        #pragma unroll
        for (int k = 0; k < 7; k++) {
            int i = t + k * 256;
            int row = i >> 6;
            int col = i & 63;
            sm_pose4[row * 64 + col] =
                gpose4[((size_t)(b * NS + sbase + row) * CC + cbase) * 4 + col];
        }
        for (int i = t; i < SCHUNK * CPB; i += 256) {
            int row = i >> 4, cc = i & 15;
            sm_act[i] = act[(size_t)(b * NS + sbase + row) * CC + cbase + cc];
        }
        // w tile: 16 ch x 10 o x 8 packed pairs
        for (int i = t; i < CPB * OO * 8; i += 256) {
            int cl = i >> 6;                 // /80... careful: 80 per channel
            cl = i / 80;
            int rem = i - cl * 80;
            int oo = rem >> 3, hp = rem & 7;
            const float* wsrc = &w[(((cbase + cl) * OO) + oo) * 16 + 2 * hp];
            sm_w2[(cl * OO + oo) * 9 + hp] = pk(wsrc[0], wsrc[1]);
        }
    }
    if (t < 80) {
        int oo = t >> 3, hp = t & 7;
        const float* pp = &g_par[par_idx][(b * OO + oo) * ACC_STRIDE];
        sm_Sh2[oo][hp]   = pk(pp[1 + 2 * hp], pp[2 + 2 * hp]);
        sm_nMSh2[oo][hp] = pk(-pp[17 + 2 * hp], -pp[18 + 2 * hp]);
    } else if (t < 90) {
        int oo = t - 80;
        sm_c1[oo] = g_par[par_idx][(b * OO + oo) * ACC_STRIDE];
    }
    __syncthreads();
    const float c1r = sm_c1[o];
    const ull* wrow = &sm_w2[(c_local * OO + o_ld) * 9];

    float a0 = 0.0f;
    ull a1p[8], a2p[8];
    #pragma unroll
    for (int hp = 0; hp < 8; hp++) { a1p[hp] = 0ULL; a2p[hp] = 0ULL; }

    const int base_row = sbase / SD;

    #pragma unroll 2
    for (int si = 0; si < SCHUNK; si++) {
        const float4* p4 = &sm_pose4[(si * CPB + c_local) * 4];
        ull v2[8];
        #pragma unroll
        for (int i = 0; i < 4; i++) {
            float4 p = p4[i];
            ull px = pk(p.x, p.x), py = pk(p.y, p.y);
            ull pz = pk(p.z, p.z), pw = pk(p.w, p.w);
            #pragma unroll
            for (int kp = 0; kp < 2; kp++) {
                ull tv = mul2(px, wrow[0 * 2 + kp]);
                tv = fma2(py, wrow[1 * 2 + kp], tv);
                tv = fma2(pz, wrow[2 * 2 + kp], tv);
                tv = fma2(pw, wrow[3 * 2 + kp], tv);
                v2[i * 2 + kp] = tv;
            }
        }
        const int row1 = (si >= SD) ? 1 : 0;
        v2[0] = add2(v2[0], pk((base_row + row1 + 0.5f) * (1.0f / SD),
                               (si - row1 * SD + 0.5f) * (1.0f / SD)));

        const float a = sm_act[si * CPB + c_local];
        ull sqa = 0ULL, sqb = 0ULL;
        #pragma unroll
        for (int hp = 0; hp < 8; hp += 2) {
            ull dA = fma2(v2[hp],     sm_Sh2[o][hp],     sm_nMSh2[o][hp]);
            ull dB = fma2(v2[hp + 1], sm_Sh2[o][hp + 1], sm_nMSh2[o][hp + 1]);
            sqa = fma2(dA, dA, sqa);
            sqb = fma2(dB, dB, sqb);
        }
        float qa0, qa1, qb0, qb1;
        upk(qa0, qa1, sqa); upk(qb0, qb1, sqb);
        float lap = c1r - ((qa0 + qa1) + (qb0 + qb1));
        float e = exp2f(lap);
        float sum = e;
        #pragma unroll
        for (int m = 8; m >= 1; m >>= 1)
            sum += __shfl_xor_sync(0xFFFFFFFFu, sum, m);
        if (__any_sync(0xFFFFFFFFu, sum < 1e-30f)) {
            float mx = lap;
            #pragma unroll
            for (int m = 8; m >= 1; m >>= 1)
                mx = fmaxf(mx, __shfl_xor_sync(0xFFFFFFFFu, mx, m));
            e = exp2f(lap - mx);
            sum = e;
            #pragma unroll
            for (int m = 8; m >= 1; m >>= 1)
                sum += __shfl_xor_sync(0xFFFFFFFFu, sum, m);
        }
        float r = e * __fdividef(a, sum);

        a0 += r;
        ull r2 = pk(r, r);
        #pragma unroll
        for (int hp = 0; hp < 8; hp++) {
            ull rv = mul2(r2, v2[hp]);
            a1p[hp] = add2(a1p[hp], rv);
            a2p[hp] = fma2(rv, v2[hp], a2p[hp]);
        }
    }

    float a1[16], a2[16];
    #pragma unroll
    for (int hp = 0; hp < 8; hp++) {
        upk(a1[2 * hp], a1[2 * hp + 1], a1p[hp]);
        upk(a2[2 * hp], a2[2 * hp + 1], a2p[hp]);
    }

    a0 += __shfl_down_sync(0xFFFFFFFFu, a0, 16);
    #pragma unroll
    for (int h = 0; h < 16; h++) {
        a1[h] += __shfl_down_sync(0xFFFFFFFFu, a1[h], 16);
        a2[h] += __shfl_down_sync(0xFFFFFFFFu, a2[h], 16);
    }

    if ((t & 31) < OO) {
        float* dst = &g_acc[acc_idx][(b * OO + o) * ACC_STRIDE];
        atomicAdd(dst, a0);
        #pragma unroll
        for (int h = 0; h < 16; h++) {
            atomicAdd(dst + 1 + h, a1[h]);
            atomicAdd(dst + 17 + h, a2[h]);
        }
    }
}

// ---------------------------------------------------------------------------
// M-step, parallelized over (b,o,h): 16 blocks x 640 thr (4 batches/block).
// ---------------------------------------------------------------------------
__global__ __launch_bounds__(640)
void m_kernel(const float* __restrict__ beta_a,
              const float* __restrict__ beta_v,
              float* __restrict__ out,
              int acc_idx, int par_idx,
              float inv_temp, int is_final)
{
    __shared__ float sc1[4][OO];
    const int t = threadIdx.x;
    const int h = t & 15;
    const int o = (t >> 4) % OO;
    const int bl = t / (OO * 16);          // 0..3
    const int b = blockIdx.x * 4 + bl;
    const int idx = b * OO + o;

    const float* sacc = &g_acc[acc_idx][idx * ACC_STRIDE];
    const float s0 = sacc[0];
    const float denom = __fdividef(1.0f, s0 + EPSV);

    const float s1 = sacc[1 + h];
    const float s2 = sacc[17 + h];
    const float mh = s1 * denom;
    const float num = s2 - 2.0f * mh * s1 + mh * mh * s0;
    const float vh = num * denom + EPSV;

    float sumlog = __logf(vh);
    #pragma unroll
    for (int m = 8; m >= 1; m >>= 1)
        sumlog += __shfl_xor_sync(0xFFFFFFFFu, sumlog, m);

    const float cost = (16.0f * beta_v[o] + 0.5f * sumlog) * s0;
    const float aj = __fdividef(1.0f, 1.0f + __expf(-inv_temp * (beta_a[o] - cost)));

    if (is_final) {
        out[idx * 16 + h] = mh;
        if (h == 0) out[BO * 16 + idx] = aj;
    } else {
        float* pp = &g_par[par_idx][idx * ACC_STRIDE];
        const float S = 0.84932180028801904f * rsqrtf(vh);  // sqrt(log2e/2)/sqrt(var)
        pp[1 + h] = S;
        pp[17 + h] = mh * S;
        const float c1l2 = (__logf(aj + EPSV)
                            - 0.5f * (16.0f * LN2PI + sumlog)) * LOG2E;
        if (h == 0) sc1[bl][o] = c1l2;
        __syncthreads();
        if (h == 0) {
            float mx = sc1[bl][0];
            #pragma unroll
            for (int oo = 1; oo < OO; oo++) mx = fmaxf(mx, sc1[bl][oo]);
            pp[0] = c1l2 - mx;
        }
    }
}

extern "C" void kernel_launch(void* const* d_in, const int* in_sizes, int n_in,
                              void* d_out, int out_size)
{
    const float* pose = (const float*)d_in[0];
    const float* act  = (const float*)d_in[1];
    const float* w    = (const float*)d_in[2];
    const float* ba   = (const float*)d_in[3];
    const float* bv   = (const float*)d_in[4];
    float* out = (float*)d_out;

    zero_kernel<<<(NZERO + 255) / 256, 256>>>();

    const float it0 = 0.01f * (1.0f - 0.95f);
    const float it1 = 0.01f * (1.0f - 0.95f * 0.95f);
    const float it2 = 0.01f * (1.0f - 0.95f * 0.95f * 0.95f);

    // iteration 0 via pose moments (no vote sweep)
    moment_kernel<<<dim3(BB, 2), dim3(32, 8)>>>(pose, act);
    init_stats_kernel<<<10, 256>>>(w);
    m_kernel<<<16, 640>>>(ba, bv, out, 0, 0, it0, 0);

    // iterations 1-2: fused rr-update + stats sweeps
    dim3 grid(NBLK_S, 2, BB);
    pass_kernel<<<grid, 256>>>(pose, act, w, 0, 1);
    m_kernel<<<16, 640>>>(ba, bv, out, 1, 1, it1, 0);
    pass_kernel<<<grid, 256>>>(pose, act, w, 1, 2);
    m_kernel<<<16, 640>>>(ba, bv, out, 2, 0, it2, 1);
}